// round 13
// baseline (speedup 1.0000x reference)
#include <cuda_runtime.h>
#include <cuda_bf16.h>
#include <math.h>
#include <stdint.h>

#define B_  8
#define ROWS 8192
#define H1W 256
#define Z_OFF     ((size_t)0)
#define ATTN_OFF  ((size_t)8192)
#define SIGMA_OFF ((size_t)8192 + (size_t)B_*16*1024*1024)

// -------- scratch --------
__device__ uint32_t g_xph[ROWS*512], g_xpl[ROWS*512];   // X pairs [row][kp]
__device__ float    g_xtf[ROWS*1024];                   // X tf32-rounded
__device__ uint32_t g_wph[512*2304], g_wpl[512*2304];   // W concat [kp][Q|K|u1]
__device__ float    g_wvg[1024*2048];                   // W concat tf32 [k][V|G]
__device__ uint32_t g_qph[ROWS*512], g_qpl[ROWS*512];
__device__ uint32_t g_kph[ROWS*512], g_kpl[ROWS*512];
__device__ float    g_vh [ROWS*1024];
__device__ float    g_gate[ROWS*1024];
__device__ float    g_h1[ROWS*H1W];
__device__ float    g_sigma[ROWS];
__device__ float    g_part[B_*16*32*64];

// -------- helpers --------
static __device__ __forceinline__ uint32_t f2tf32(float f){
    uint32_t r; asm("cvt.rna.tf32.f32 %0, %1;" : "=r"(r) : "f"(f)); return r;
}
static __device__ __forceinline__ float tf32f(float f){ return __uint_as_float(f2tf32(f)); }
static __device__ __forceinline__ void splitb(float v, uint32_t& h, uint32_t& l){
    __nv_bfloat16 bh = __float2bfloat16_rn(v);
    __nv_bfloat16 bl = __float2bfloat16_rn(v - __bfloat162float(bh));
    h = (uint32_t)__bfloat16_as_ushort(bh); l = (uint32_t)__bfloat16_as_ushort(bl);
}
static __device__ __forceinline__ void mma16(float* c, const uint32_t* a, const uint32_t* b){
    asm volatile("mma.sync.aligned.m16n8k16.row.col.f32.bf16.bf16.f32 "
        "{%0,%1,%2,%3}, {%4,%5,%6,%7}, {%8,%9}, {%0,%1,%2,%3};"
        : "+f"(c[0]), "+f"(c[1]), "+f"(c[2]), "+f"(c[3])
        : "r"(a[0]), "r"(a[1]), "r"(a[2]), "r"(a[3]), "r"(b[0]), "r"(b[1]));
}
static __device__ __forceinline__ void mma8(float* c, const uint32_t* a, const uint32_t* b){
    asm volatile("mma.sync.aligned.m16n8k8.row.col.f32.tf32.tf32.f32 "
        "{%0,%1,%2,%3}, {%4,%5,%6,%7}, {%8,%9}, {%0,%1,%2,%3};"
        : "+f"(c[0]), "+f"(c[1]), "+f"(c[2]), "+f"(c[3])
        : "r"(a[0]), "r"(a[1]), "r"(a[2]), "r"(a[3]), "r"(b[0]), "r"(b[1]));
}

// ============================================================
// conv_x: split X into bf16 hi/lo pairs + tf32 copy
// ============================================================
__global__ __launch_bounds__(256) void conv_x_kernel(const float* __restrict__ x){
    size_t gid = (size_t)blockIdx.x*256 + threadIdx.x;
    float4 v = ((const float4*)x)[gid];
    uint32_t h0,l0,h1,l1,h2,l2,h3,l3;
    splitb(v.x,h0,l0); splitb(v.y,h1,l1); splitb(v.z,h2,l2); splitb(v.w,h3,l3);
    g_xph[gid*2]   = h0 | (h1<<16);  g_xpl[gid*2]   = l0 | (l1<<16);
    g_xph[gid*2+1] = h2 | (h3<<16);  g_xpl[gid*2+1] = l2 | (l3<<16);
    float4 tv = make_float4(tf32f(v.x), tf32f(v.y), tf32f(v.z), tf32f(v.w));
    ((float4*)g_xtf)[gid] = tv;
}

// ============================================================
// conv_w: split + concat Q|K|u1 weights: g_wp*[kp][2304]
// ============================================================
__global__ __launch_bounds__(256) void conv_w_kernel(
    const float* __restrict__ Wq, const float* __restrict__ Wk,
    const float* __restrict__ Wu1)
{
    int idx = blockIdx.x*256 + threadIdx.x;   // 512*576
    int kp = idx / 576, n = (idx % 576) * 4;
    const float* W; int wld, nl;
    if (n < 1024)      { W=Wq;  wld=1024; nl=n; }
    else if (n < 2048) { W=Wk;  wld=1024; nl=n-1024; }
    else               { W=Wu1; wld=256;  nl=n-2048; }
    float4 a = *(const float4*)&W[(size_t)(2*kp    )*wld + nl];
    float4 b = *(const float4*)&W[(size_t)(2*kp + 1)*wld + nl];
    const float a4[4] = {a.x,a.y,a.z,a.w};
    const float b4[4] = {b.x,b.y,b.z,b.w};
#pragma unroll
    for (int c = 0; c < 4; c++) {
        uint32_t h0,l0,h1,l1;
        splitb(a4[c],h0,l0); splitb(b4[c],h1,l1);
        g_wph[(size_t)kp*2304 + n + c] = h0 | (h1<<16);
        g_wpl[(size_t)kp*2304 + n + c] = l0 | (l1<<16);
    }
}

// ============================================================
// conv_wvg: concat V|G weights as tf32: g_wvg[k][2048]
// ============================================================
__global__ __launch_bounds__(256) void conv_wvg_kernel(
    const float* __restrict__ Wv, const float* __restrict__ Wg)
{
    size_t pos = ((size_t)blockIdx.x*256 + threadIdx.x) * 4;   // 2048 blocks
    int k = (int)(pos >> 11), n = (int)(pos & 2047);
    const float* W = (n < 1024) ? Wv : Wg;
    int nl = n & 1023;
    float4 v = *(const float4*)&W[(size_t)k*1024 + nl];
    float4 tv = make_float4(tf32f(v.x), tf32f(v.y), tf32f(v.z), tf32f(v.w));
    *(float4*)&g_wvg[pos] = tv;
}

// ============================================================
// proj_qkh: bf16x3 GEMM for Q|K|H1 (N=2304), reg-prefetch
// ============================================================
__global__ __launch_bounds__(256) void proj_qkh_kernel(
    const float* __restrict__ bq, const float* __restrict__ bk,
    const float* __restrict__ bu1)
{
    __shared__ uint32_t Xh[128][12], Xl[128][12];
    __shared__ uint32_t Wh[8][136],  Wl[8][136];

    const int rowt = blockIdx.x * 128;
    const int colt = blockIdx.y * 128;
    const float* bias; int lcol, sec;
    if (colt < 1024)      { bias=bq;  lcol=colt;      sec=0; }
    else if (colt < 2048) { bias=bk;  lcol=colt-1024; sec=1; }
    else                  { bias=bu1; lcol=colt-2048; sec=4; }

    const int tid = threadIdx.x;
    const int w = tid >> 5, lane = tid & 31;
    const int g = lane >> 2, t = lane & 3;
    const int m0w = (w & 3) * 32;
    const int n0w = (w >> 2) * 64;

    const int xr = tid >> 1, xq = (tid & 1) * 4;
    const int wkp = tid >> 5, wn4 = (lane) << 2;

    float acc[2][8][4];
#pragma unroll
    for (int i=0;i<2;i++)
#pragma unroll
        for (int j=0;j<8;j++)
#pragma unroll
            for (int r=0;r<4;r++) acc[i][j][r] = 0.f;

    uint4 pxh, pxl, pwh, pwl;
    {
        size_t xs = (size_t)(rowt + xr)*512 + xq;
        pxh = *(const uint4*)&g_xph[xs];  pxl = *(const uint4*)&g_xpl[xs];
        size_t ws = (size_t)wkp*2304 + colt + wn4;
        pwh = *(const uint4*)&g_wph[ws];  pwl = *(const uint4*)&g_wpl[ws];
    }

    for (int kc = 0; kc < 64; kc++) {
        __syncthreads();
        *(uint4*)&Xh[xr][xq] = pxh;  *(uint4*)&Xl[xr][xq] = pxl;
        *(uint4*)&Wh[wkp][wn4] = pwh; *(uint4*)&Wl[wkp][wn4] = pwl;
        __syncthreads();
        if (kc < 63) {
            size_t xs = (size_t)(rowt + xr)*512 + (kc+1)*8 + xq;
            pxh = *(const uint4*)&g_xph[xs];  pxl = *(const uint4*)&g_xpl[xs];
            size_t ws = (size_t)((kc+1)*8 + wkp)*2304 + colt + wn4;
            pwh = *(const uint4*)&g_wph[ws];  pwl = *(const uint4*)&g_wpl[ws];
        }
        uint32_t aH[2][4], aL[2][4];
#pragma unroll
        for (int i = 0; i < 2; i++) {
            aH[i][0]=Xh[m0w+i*16+g  ][t];   aH[i][1]=Xh[m0w+i*16+g+8][t];
            aH[i][2]=Xh[m0w+i*16+g  ][t+4]; aH[i][3]=Xh[m0w+i*16+g+8][t+4];
            aL[i][0]=Xl[m0w+i*16+g  ][t];   aL[i][1]=Xl[m0w+i*16+g+8][t];
            aL[i][2]=Xl[m0w+i*16+g  ][t+4]; aL[i][3]=Xl[m0w+i*16+g+8][t+4];
        }
#pragma unroll
        for (int j = 0; j < 8; j++) {
            int n = n0w + j*8 + g;
            uint32_t bH[2] = {Wh[t][n], Wh[t+4][n]};
            uint32_t bL[2] = {Wl[t][n], Wl[t+4][n]};
#pragma unroll
            for (int i = 0; i < 2; i++) {
                mma16(acc[i][j], aH[i], bH);
                mma16(acc[i][j], aH[i], bL);
                mma16(acc[i][j], aL[i], bH);
            }
        }
    }

#pragma unroll
    for (int i = 0; i < 2; i++) {
#pragma unroll
        for (int j = 0; j < 8; j++) {
            int lc = lcol + n0w + j*8 + 2*t;
            float b0 = bias[lc], b1 = bias[lc+1];
            float c0 = acc[i][j][0] + b0, c1 = acc[i][j][1] + b1;
            float c2 = acc[i][j][2] + b0, c3 = acc[i][j][3] + b1;
            int gr = rowt + m0w + i*16 + g;
            if (sec <= 1) {
                uint32_t* oph = sec==0 ? g_qph : g_kph;
                uint32_t* opl = sec==0 ? g_qpl : g_kpl;
                uint32_t h0,l0,h1,l1,h2,l2,h3,l3;
                splitb(c0,h0,l0); splitb(c1,h1,l1); splitb(c2,h2,l2); splitb(c3,h3,l3);
                int pc = lc >> 1;
                oph[(size_t)gr*512 + pc]     = h0 | (h1<<16);
                opl[(size_t)gr*512 + pc]     = l0 | (l1<<16);
                oph[(size_t)(gr+8)*512 + pc] = h2 | (h3<<16);
                opl[(size_t)(gr+8)*512 + pc] = l2 | (l3<<16);
            } else {
                c0=fmaxf(c0,0.f); c1=fmaxf(c1,0.f); c2=fmaxf(c2,0.f); c3=fmaxf(c3,0.f);
                *(float2*)&g_h1[(size_t)gr*H1W + lc]     = make_float2(c0,c1);
                *(float2*)&g_h1[(size_t)(gr+8)*H1W + lc] = make_float2(c2,c3);
            }
        }
    }
}

// ============================================================
// proj_vg: tf32-single GEMM for V|G, pre-converted inputs,
// 512 threads, 32x32 warp tiles, reg-prefetch
// ============================================================
__global__ __launch_bounds__(512) void proj_vg_kernel(
    const float* __restrict__ bv, const float* __restrict__ bg)
{
    __shared__ uint32_t Xs[128][20];   // [m][k]
    __shared__ uint32_t Ws[16][136];   // [k][n]

    const int rowt = blockIdx.x * 128;
    const int colt = blockIdx.y * 128;
    const float* bias; int lcol, sec;
    if (colt < 1024) { bias=bv; lcol=colt;      sec=2; }
    else             { bias=bg; lcol=colt-1024; sec=3; }

    const int tid = threadIdx.x;
    const int w   = tid >> 5, lane = tid & 31;
    const int g   = lane >> 2, t = lane & 3;
    const int m0w = (w & 3) * 32;
    const int n0w = (w >> 2) * 32;

    // loader coords
    const int xr = tid >> 2, xq = (tid & 3) << 2;     // X: 128 rows x 16k
    const int wkr = tid >> 5, wc4 = (lane) << 2;      // W: 16k x 128n

    float acc[2][4][4];
#pragma unroll
    for (int i = 0; i < 2; i++)
#pragma unroll
        for (int j = 0; j < 4; j++)
#pragma unroll
            for (int r = 0; r < 4; r++) acc[i][j][r] = 0.f;

    uint4 px, pw;
    {
        px = *(const uint4*)&g_xtf[(size_t)(rowt + xr)*1024 + xq];
        pw = *(const uint4*)&g_wvg[(size_t)wkr*2048 + colt + wc4];
    }

    for (int kc = 0; kc < 64; kc++) {
        __syncthreads();
        *(uint4*)&Xs[xr][xq] = px;
        *(uint4*)&Ws[wkr][wc4] = pw;
        __syncthreads();
        if (kc < 63) {
            px = *(const uint4*)&g_xtf[(size_t)(rowt + xr)*1024 + (kc+1)*16 + xq];
            pw = *(const uint4*)&g_wvg[(size_t)((kc+1)*16 + wkr)*2048 + colt + wc4];
        }
#pragma unroll
        for (int ks = 0; ks < 16; ks += 8) {
            uint32_t a[2][4];
#pragma unroll
            for (int i = 0; i < 2; i++) {
                a[i][0] = Xs[m0w + i*16 + g    ][ks + t];
                a[i][1] = Xs[m0w + i*16 + g + 8][ks + t];
                a[i][2] = Xs[m0w + i*16 + g    ][ks + t + 4];
                a[i][3] = Xs[m0w + i*16 + g + 8][ks + t + 4];
            }
#pragma unroll
            for (int j = 0; j < 4; j++) {
                uint32_t b[2];
                b[0] = Ws[ks + t    ][n0w + j*8 + g];
                b[1] = Ws[ks + t + 4][n0w + j*8 + g];
                mma8(acc[0][j], a[0], b);
                mma8(acc[1][j], a[1], b);
            }
        }
    }

#pragma unroll
    for (int i = 0; i < 2; i++) {
#pragma unroll
        for (int j = 0; j < 4; j++) {
            int lc = lcol + n0w + j*8 + 2*t;
            float b0 = bias[lc], b1 = bias[lc + 1];
            float c0 = acc[i][j][0] + b0, c1 = acc[i][j][1] + b1;
            float c2 = acc[i][j][2] + b0, c3 = acc[i][j][3] + b1;
            int gr = rowt + m0w + i*16 + g;
            if (sec == 2) {
                *(float2*)&g_vh[(size_t)gr*1024 + lc]     = make_float2(tf32f(c0), tf32f(c1));
                *(float2*)&g_vh[(size_t)(gr+8)*1024 + lc] = make_float2(tf32f(c2), tf32f(c3));
            } else {
                c0=1.f/(1.f+__expf(-c0)); c1=1.f/(1.f+__expf(-c1));
                c2=1.f/(1.f+__expf(-c2)); c3=1.f/(1.f+__expf(-c3));
                *(float2*)&g_gate[(size_t)gr*1024 + lc]     = make_float2(c0,c1);
                *(float2*)&g_gate[(size_t)(gr+8)*1024 + lc] = make_float2(c2,c3);
            }
        }
    }
}

// ============================================================
// sigma
// ============================================================
__global__ __launch_bounds__(256) void sigma_kernel(
    const float* __restrict__ Wu2, const float* __restrict__ bu2,
    float* __restrict__ out)
{
    const int tid = threadIdx.x, w = tid >> 5, lane = tid & 31;
    const int row = blockIdx.x * 8 + w;
    const float* hr = &g_h1[(size_t)row * H1W];
    float s = 0.f;
#pragma unroll
    for (int j = lane; j < H1W; j += 32) s += hr[j] * Wu2[j];
#pragma unroll
    for (int o = 16; o; o >>= 1) s += __shfl_xor_sync(0xFFFFFFFFu, s, o);
    if (lane == 0) {
        float v = s + bu2[0];
        float sp = (v > 15.f) ? v : log1pf(__expf(v));
        g_sigma[row] = sp + 1e-6f;
        out[SIGMA_OFF + row] = sp + 1e-6f;
    }
}

// ============================================================
// attention: 512 threads, QK^T bf16x3 (Q frags hoisted), PV tf32  [R8]
// ============================================================
#define SM_P    0          // fp32 [32][1028]
#define SM_QH   32896      // u32 [32][36]
#define SM_QL   34048
#define SM_KV   35200      // K: hi[128][36]+lo[128][36] ; V: [128][72]
#define SM_PH   44416      // fp32 [32][132]
#define SM_ISN  48640
#define SM_SCL  49664
#define SM_INVL 49696
#define SM_CS   49728      // fp32 [32][68]
#define SM_TOT  51904
#define ATTN_SMEM_BYTES (SM_TOT*4)

__global__ __launch_bounds__(512) void attn_kernel(float* __restrict__ out)
{
    extern __shared__ float sm[];
    float*    P    = sm + SM_P;
    uint32_t* QH   = (uint32_t*)(sm + SM_QH);
    uint32_t* QL   = (uint32_t*)(sm + SM_QL);
    uint32_t* KH   = (uint32_t*)(sm + SM_KV);
    uint32_t* KL   = KH + 4608;
    uint32_t* VH   = (uint32_t*)(sm + SM_KV);   // union with K
    float*    Ph   = sm + SM_PH;
    float*    isn  = sm + SM_ISN;
    float*    scl  = sm + SM_SCL;
    float*    invl = sm + SM_INVL;
    float*    Cs   = sm + SM_CS;

    const int mt = blockIdx.x, h = blockIdx.y, b = blockIdx.z;
    const int m0 = mt * 32;
    const int tid = threadIdx.x;
    const int w = tid >> 5, lane = tid & 31;
    const int g = lane >> 2, t = lane & 3;

    for (int n = tid; n < 1024; n += 512) isn[n] = 1.f / g_sigma[(b << 10) + n];
    if (tid < 32) scl[tid] = 0.125f / g_sigma[(b << 10) + m0 + tid];

    if (tid < 256) {
        int r = tid >> 3, p4 = (tid & 7) << 2;
        size_t src = ((size_t)(b << 10) + m0 + r)*512 + (h << 5) + p4;
        *(uint4*)&QH[r*36 + p4] = *(const uint4*)&g_qph[src];
        *(uint4*)&QL[r*36 + p4] = *(const uint4*)&g_qpl[src];
    }

    const int kr[2] = { tid >> 3, (tid + 512) >> 3 };
    const int kp4 = (tid & 7) << 2;
    uint4 pkh[2], pkl[2];
#pragma unroll
    for (int it = 0; it < 2; it++) {
        size_t src = ((size_t)(b << 10) + kr[it])*512 + (h << 5) + kp4;
        pkh[it] = *(const uint4*)&g_kph[src];
        pkl[it] = *(const uint4*)&g_kpl[src];
    }

    __syncthreads();

    uint32_t qHf[4][2][4], qLf[4][2][4];
#pragma unroll
    for (int s = 0; s < 4; s++) {
        int ko = s*8;
#pragma unroll
        for (int i = 0; i < 2; i++) {
            qHf[s][i][0]=QH[(i*16+g  )*36+ko+t];   qHf[s][i][1]=QH[(i*16+g+8)*36+ko+t];
            qHf[s][i][2]=QH[(i*16+g  )*36+ko+t+4]; qHf[s][i][3]=QH[(i*16+g+8)*36+ko+t+4];
            qLf[s][i][0]=QL[(i*16+g  )*36+ko+t];   qLf[s][i][1]=QL[(i*16+g+8)*36+ko+t];
            qLf[s][i][2]=QL[(i*16+g  )*36+ko+t+4]; qLf[s][i][3]=QL[(i*16+g+8)*36+ko+t+4];
        }
    }

    for (int c = 0; c < 8; c++) {
        const int n0c = c * 128;
        __syncthreads();
#pragma unroll
        for (int it = 0; it < 2; it++) {
            *(uint4*)&KH[kr[it]*36 + kp4] = pkh[it];
            *(uint4*)&KL[kr[it]*36 + kp4] = pkl[it];
        }
        __syncthreads();
        if (c < 7) {
#pragma unroll
            for (int it = 0; it < 2; it++) {
                size_t src = ((size_t)(b << 10) + (c+1)*128 + kr[it])*512 + (h << 5) + kp4;
                pkh[it] = *(const uint4*)&g_kph[src];
                pkl[it] = *(const uint4*)&g_kpl[src];
            }
        }

        float acc[2][4];
#pragma unroll
        for (int i=0;i<2;i++)
#pragma unroll
            for (int r=0;r<4;r++) acc[i][r] = 0.f;

        const int n = w*8 + g;
#pragma unroll
        for (int s = 0; s < 4; s++) {
            int ko = s*8;
            uint32_t bH[2] = {KH[n*36+ko+t], KH[n*36+ko+t+4]};
            uint32_t bL[2] = {KL[n*36+ko+t], KL[n*36+ko+t+4]};
#pragma unroll
            for (int i = 0; i < 2; i++) {
                mma16(acc[i], qHf[s][i], bH);
                mma16(acc[i], qHf[s][i], bL);
                mma16(acc[i], qLf[s][i], bH);
            }
        }
#pragma unroll
        for (int i = 0; i < 2; i++) {
            int r0 = i*16 + g, r1 = r0 + 8;
            int nl = w*8 + 2*t;
            P[r0*1028 + n0c + nl    ] = __expf(acc[i][0]*scl[r0]*isn[n0c+nl]);
            P[r0*1028 + n0c + nl + 1] = __expf(acc[i][1]*scl[r0]*isn[n0c+nl+1]);
            P[r1*1028 + n0c + nl    ] = __expf(acc[i][2]*scl[r1]*isn[n0c+nl]);
            P[r1*1028 + n0c + nl + 1] = __expf(acc[i][3]*scl[r1]*isn[n0c+nl+1]);
        }
    }

    const int vr[4] = { tid>>4, (tid+512)>>4, (tid+1024)>>4, (tid+1536)>>4 };
    const int vc4 = (tid & 15) << 2;
    uint4 pv[4];
#pragma unroll
    for (int it = 0; it < 4; it++)
        pv[it] = *(const uint4*)&g_vh[((size_t)(b << 10) + vr[it])*1024 + (h << 6) + vc4];

    __syncthreads();
#pragma unroll
    for (int r = w*2; r < w*2 + 2; r++) {
        float s = 0.f;
        for (int n = lane; n < 1024; n += 32) s += P[r*1028 + n];
#pragma unroll
        for (int o = 16; o; o >>= 1) s += __shfl_xor_sync(0xFFFFFFFFu, s, o);
        if (lane == 0) invl[r] = 1.f / s;
    }
    __syncthreads();

    {
        const size_t base = ATTN_OFF + (((size_t)(b*16 + h))*1024 + m0)*1024;
        for (int e = tid; e < 32*256; e += 512) {
            int i = e >> 8, n4 = (e & 255) << 2;
            float4 p = *(float4*)&P[i*1028 + n4];
            float iv = invl[i];
            p.x*=iv; p.y*=iv; p.z*=iv; p.w*=iv;
            *(float4*)&out[base + (size_t)i*1024 + n4] = p;
        }
    }

    float cacc[4] = {0.f, 0.f, 0.f, 0.f};
    const int ihalf = w >> 3, d0 = (w & 7) * 8;
    const int pr = tid >> 4, pjb = (tid & 15) << 3;

    for (int c = 0; c < 8; c++) {
        const int n0c = c * 128;
        __syncthreads();
#pragma unroll
        for (int it = 0; it < 4; it++)
            *(uint4*)&VH[vr[it]*72 + vc4] = pv[it];
#pragma unroll
        for (int jj = 0; jj < 8; jj++)
            Ph[pr*132 + pjb + jj] = tf32f(P[pr*1028 + n0c + pjb + jj]);
        __syncthreads();
        if (c < 7) {
#pragma unroll
            for (int it = 0; it < 4; it++)
                pv[it] = *(const uint4*)&g_vh[((size_t)(b << 10) + (c+1)*128 + vr[it])*1024 + (h << 6) + vc4];
        }
#pragma unroll
        for (int ks = 0; ks < 128; ks += 8) {
            uint32_t aH[4];
            aH[0]=__float_as_uint(Ph[(ihalf*16+g  )*132+ks+t]);
            aH[1]=__float_as_uint(Ph[(ihalf*16+g+8)*132+ks+t]);
            aH[2]=__float_as_uint(Ph[(ihalf*16+g  )*132+ks+t+4]);
            aH[3]=__float_as_uint(Ph[(ihalf*16+g+8)*132+ks+t+4]);
            uint32_t bb[2] = {VH[(ks+t)*72 + d0 + g], VH[(ks+t+4)*72 + d0 + g]};
            mma8(cacc, aH, bb);
        }
    }
    __syncthreads();

    {
        int r0 = ihalf*16 + g, r1 = r0 + 8;
        int d = d0 + 2*t;
        float g0 = g_gate[((size_t)(b<<10) + m0 + r0)*1024 + (h<<6) + d];
        float g1 = g_gate[((size_t)(b<<10) + m0 + r0)*1024 + (h<<6) + d + 1];
        float g2 = g_gate[((size_t)(b<<10) + m0 + r1)*1024 + (h<<6) + d];
        float g3 = g_gate[((size_t)(b<<10) + m0 + r1)*1024 + (h<<6) + d + 1];
        Cs[r0*68 + d    ] = cacc[0] * invl[r0] * g0;
        Cs[r0*68 + d + 1] = cacc[1] * invl[r0] * g1;
        Cs[r1*68 + d    ] = cacc[2] * invl[r1] * g2;
        Cs[r1*68 + d + 1] = cacc[3] * invl[r1] * g3;
    }
    __syncthreads();
    if (tid < 64) {
        float s = 0.f;
#pragma unroll
        for (int i = 0; i < 32; i++) s += Cs[i*68 + tid];
        g_part[(((b << 4) + h)*32 + mt)*64 + tid] = s * (1.f/1024.f);
    }
}

// ============================================================
// z = colmean @ Wo + bo
// ============================================================
__global__ __launch_bounds__(256) void z_kernel(
    const float* __restrict__ Wo, const float* __restrict__ bo,
    float* __restrict__ out)
{
    __shared__ float cm[1024];
    __shared__ float red[4][64];
    const int b = blockIdx.x, oc = blockIdx.y;

    for (int c = threadIdx.x; c < 1024; c += 256) {
        int hh = c >> 6, d = c & 63;
        const float* pp = &g_part[(size_t)(((b << 4) + hh)*32)*64 + d];
        float s = 0.f;
#pragma unroll
        for (int tt = 0; tt < 32; tt++) s += pp[tt*64];
        cm[c] = s;
    }
    __syncthreads();

    const int oi = threadIdx.x & 63, ks = threadIdx.x >> 6;
    const int o = oc*64 + oi;
    float s = 0.f;
#pragma unroll 4
    for (int k = ks*256; k < ks*256 + 256; k++) s += cm[k] * Wo[(size_t)k*1024 + o];
    red[ks][oi] = s;
    __syncthreads();
    if (threadIdx.x < 64) {
        float r = red[0][threadIdx.x] + red[1][threadIdx.x]
                + red[2][threadIdx.x] + red[3][threadIdx.x] + bo[oc*64 + threadIdx.x];
        out[Z_OFF + (size_t)b*1024 + oc*64 + threadIdx.x] = r;
    }
}

// ============================================================
extern "C" void kernel_launch(void* const* d_in, const int* in_sizes, int n_in,
                              void* d_out, int out_size)
{
    const float* x   = (const float*)d_in[0];
    const float* Wq  = (const float*)d_in[1];
    const float* bq  = (const float*)d_in[2];
    const float* Wk  = (const float*)d_in[3];
    const float* bk  = (const float*)d_in[4];
    const float* Wv  = (const float*)d_in[5];
    const float* bv  = (const float*)d_in[6];
    const float* Wg  = (const float*)d_in[7];
    const float* bg  = (const float*)d_in[8];
    const float* Wo  = (const float*)d_in[9];
    const float* bo  = (const float*)d_in[10];
    const float* Wu1 = (const float*)d_in[11];
    const float* bu1 = (const float*)d_in[12];
    const float* Wu2 = (const float*)d_in[13];
    const float* bu2 = (const float*)d_in[14];
    float* out = (float*)d_out;

    conv_x_kernel<<<8192, 256>>>(x);
    conv_w_kernel<<<1152, 256>>>(Wq, Wk, Wu1);
    conv_wvg_kernel<<<2048, 256>>>(Wv, Wg);
    proj_qkh_kernel<<<dim3(64, 18), 256>>>(bq, bk, bu1);
    proj_vg_kernel<<<dim3(64, 16), 512>>>(bv, bg);
    sigma_kernel<<<1024, 256>>>(Wu2, bu2, out);
    cudaFuncSetAttribute(attn_kernel, cudaFuncAttributeMaxDynamicSharedMemorySize,
                         ATTN_SMEM_BYTES);
    attn_kernel<<<dim3(32, 16, 8), 512, ATTN_SMEM_BYTES>>>(out);
    z_kernel<<<dim3(8, 16), 256>>>(Wo, bo, out);
}

// round 15
// speedup vs baseline: 1.4652x; 1.4652x over previous
#include <cuda_runtime.h>
#include <cuda_bf16.h>
#include <math.h>
#include <stdint.h>

#define B_  8
#define ROWS 8192
#define H1W 256
#define Z_OFF     ((size_t)0)
#define ATTN_OFF  ((size_t)8192)
#define SIGMA_OFF ((size_t)8192 + (size_t)B_*16*1024*1024)

// -------- scratch --------
__device__ uint32_t g_xph[ROWS*512], g_xpl[ROWS*512];   // X pairs [row][kp]
__device__ float    g_xtf[ROWS*1024];                   // X tf32-rounded
__device__ uint32_t g_wph[512*2304], g_wpl[512*2304];   // W concat [kp][Q|K|u1]
__device__ float    g_wvg[1024*2048];                   // W concat tf32 [k][V|G]
__device__ uint32_t g_qph[ROWS*512], g_qpl[ROWS*512];
__device__ uint32_t g_kph[ROWS*512], g_kpl[ROWS*512];
__device__ float    g_vh [ROWS*1024];
__device__ float    g_gate[ROWS*1024];
__device__ float    g_h1[ROWS*H1W];
__device__ float    g_sigma[ROWS];
__device__ float    g_part[B_*16*32*64];

// -------- helpers --------
static __device__ __forceinline__ uint32_t f2tf32(float f){
    uint32_t r; asm("cvt.rna.tf32.f32 %0, %1;" : "=r"(r) : "f"(f)); return r;
}
static __device__ __forceinline__ float tf32f(float f){ return __uint_as_float(f2tf32(f)); }
static __device__ __forceinline__ void splitb(float v, uint32_t& h, uint32_t& l){
    __nv_bfloat16 bh = __float2bfloat16_rn(v);
    __nv_bfloat16 bl = __float2bfloat16_rn(v - __bfloat162float(bh));
    h = (uint32_t)__bfloat16_as_ushort(bh); l = (uint32_t)__bfloat16_as_ushort(bl);
}
static __device__ __forceinline__ void mma16(float* c, const uint32_t* a, const uint32_t* b){
    asm volatile("mma.sync.aligned.m16n8k16.row.col.f32.bf16.bf16.f32 "
        "{%0,%1,%2,%3}, {%4,%5,%6,%7}, {%8,%9}, {%0,%1,%2,%3};"
        : "+f"(c[0]), "+f"(c[1]), "+f"(c[2]), "+f"(c[3])
        : "r"(a[0]), "r"(a[1]), "r"(a[2]), "r"(a[3]), "r"(b[0]), "r"(b[1]));
}
static __device__ __forceinline__ void mma8(float* c, const uint32_t* a, const uint32_t* b){
    asm volatile("mma.sync.aligned.m16n8k8.row.col.f32.tf32.tf32.f32 "
        "{%0,%1,%2,%3}, {%4,%5,%6,%7}, {%8,%9}, {%0,%1,%2,%3};"
        : "+f"(c[0]), "+f"(c[1]), "+f"(c[2]), "+f"(c[3])
        : "r"(a[0]), "r"(a[1]), "r"(a[2]), "r"(a[3]), "r"(b[0]), "r"(b[1]));
}

// ============================================================
// conv_x: split X into bf16 hi/lo pairs + tf32 copy
// ============================================================
__global__ __launch_bounds__(256) void conv_x_kernel(const float* __restrict__ x){
    size_t gid = (size_t)blockIdx.x*256 + threadIdx.x;
    float4 v = ((const float4*)x)[gid];
    uint32_t h0,l0,h1,l1,h2,l2,h3,l3;
    splitb(v.x,h0,l0); splitb(v.y,h1,l1); splitb(v.z,h2,l2); splitb(v.w,h3,l3);
    g_xph[gid*2]   = h0 | (h1<<16);  g_xpl[gid*2]   = l0 | (l1<<16);
    g_xph[gid*2+1] = h2 | (h3<<16);  g_xpl[gid*2+1] = l2 | (l3<<16);
    float4 tv = make_float4(tf32f(v.x), tf32f(v.y), tf32f(v.z), tf32f(v.w));
    ((float4*)g_xtf)[gid] = tv;
}

// ============================================================
// conv_w: split + concat Q|K|u1 weights: g_wp*[kp][2304]
// ============================================================
__global__ __launch_bounds__(256) void conv_w_kernel(
    const float* __restrict__ Wq, const float* __restrict__ Wk,
    const float* __restrict__ Wu1)
{
    int idx = blockIdx.x*256 + threadIdx.x;   // 512*576
    int kp = idx / 576, n = (idx % 576) * 4;
    const float* W; int wld, nl;
    if (n < 1024)      { W=Wq;  wld=1024; nl=n; }
    else if (n < 2048) { W=Wk;  wld=1024; nl=n-1024; }
    else               { W=Wu1; wld=256;  nl=n-2048; }
    float4 a = *(const float4*)&W[(size_t)(2*kp    )*wld + nl];
    float4 b = *(const float4*)&W[(size_t)(2*kp + 1)*wld + nl];
    const float a4[4] = {a.x,a.y,a.z,a.w};
    const float b4[4] = {b.x,b.y,b.z,b.w};
#pragma unroll
    for (int c = 0; c < 4; c++) {
        uint32_t h0,l0,h1,l1;
        splitb(a4[c],h0,l0); splitb(b4[c],h1,l1);
        g_wph[(size_t)kp*2304 + n + c] = h0 | (h1<<16);
        g_wpl[(size_t)kp*2304 + n + c] = l0 | (l1<<16);
    }
}

// ============================================================
// conv_wvg: concat V|G weights as tf32: g_wvg[k][2048]
// ============================================================
__global__ __launch_bounds__(256) void conv_wvg_kernel(
    const float* __restrict__ Wv, const float* __restrict__ Wg)
{
    size_t pos = ((size_t)blockIdx.x*256 + threadIdx.x) * 4;
    int k = (int)(pos >> 11), n = (int)(pos & 2047);
    const float* W = (n < 1024) ? Wv : Wg;
    int nl = n & 1023;
    float4 v = *(const float4*)&W[(size_t)k*1024 + nl];
    float4 tv = make_float4(tf32f(v.x), tf32f(v.y), tf32f(v.z), tf32f(v.w));
    *(float4*)&g_wvg[pos] = tv;
}

// ============================================================
// proj (combined): y<18 -> Q|K|H1 bf16x3 ; y>=18 -> V|G tf32
// smem union: qkh 5248 u32 / vg 4736 u32
// ============================================================
__global__ __launch_bounds__(256) void proj_kernel(
    const float* __restrict__ bq, const float* __restrict__ bk,
    const float* __restrict__ bu1,
    const float* __restrict__ bv, const float* __restrict__ bg)
{
    __shared__ __align__(16) uint32_t SB[5248];

    const int rowt = blockIdx.x * 128;
    const int tid = threadIdx.x;
    const int w = tid >> 5, lane = tid & 31;
    const int g = lane >> 2, t = lane & 3;
    const int m0w = (w & 3) * 32;
    const int n0w = (w >> 2) * 64;

    if (blockIdx.y < 18) {
        // ---------------- qkh path (bf16x3) ----------------
        uint32_t* Xh = SB;            // [128][12]
        uint32_t* Xl = SB + 1536;
        uint32_t* Wh = SB + 3072;     // [8][136]
        uint32_t* Wl = SB + 4160;

        const int colt = blockIdx.y * 128;
        const float* bias; int lcol, sec;
        if (colt < 1024)      { bias=bq;  lcol=colt;      sec=0; }
        else if (colt < 2048) { bias=bk;  lcol=colt-1024; sec=1; }
        else                  { bias=bu1; lcol=colt-2048; sec=4; }

        const int xr = tid >> 1, xq = (tid & 1) * 4;
        const int wkp = tid >> 5, wn4 = lane << 2;

        float acc[2][8][4];
#pragma unroll
        for (int i=0;i<2;i++)
#pragma unroll
            for (int j=0;j<8;j++)
#pragma unroll
                for (int r=0;r<4;r++) acc[i][j][r] = 0.f;

        uint4 pxh, pxl, pwh, pwl;
        {
            size_t xs = (size_t)(rowt + xr)*512 + xq;
            pxh = *(const uint4*)&g_xph[xs];  pxl = *(const uint4*)&g_xpl[xs];
            size_t ws = (size_t)wkp*2304 + colt + wn4;
            pwh = *(const uint4*)&g_wph[ws];  pwl = *(const uint4*)&g_wpl[ws];
        }

        for (int kc = 0; kc < 64; kc++) {
            __syncthreads();
            *(uint4*)&Xh[xr*12 + xq] = pxh;   *(uint4*)&Xl[xr*12 + xq] = pxl;
            *(uint4*)&Wh[wkp*136 + wn4] = pwh; *(uint4*)&Wl[wkp*136 + wn4] = pwl;
            __syncthreads();
            if (kc < 63) {
                size_t xs = (size_t)(rowt + xr)*512 + (kc+1)*8 + xq;
                pxh = *(const uint4*)&g_xph[xs];  pxl = *(const uint4*)&g_xpl[xs];
                size_t ws = (size_t)((kc+1)*8 + wkp)*2304 + colt + wn4;
                pwh = *(const uint4*)&g_wph[ws];  pwl = *(const uint4*)&g_wpl[ws];
            }
            uint32_t aH[2][4], aL[2][4];
#pragma unroll
            for (int i = 0; i < 2; i++) {
                aH[i][0]=Xh[(m0w+i*16+g  )*12+t];   aH[i][1]=Xh[(m0w+i*16+g+8)*12+t];
                aH[i][2]=Xh[(m0w+i*16+g  )*12+t+4]; aH[i][3]=Xh[(m0w+i*16+g+8)*12+t+4];
                aL[i][0]=Xl[(m0w+i*16+g  )*12+t];   aL[i][1]=Xl[(m0w+i*16+g+8)*12+t];
                aL[i][2]=Xl[(m0w+i*16+g  )*12+t+4]; aL[i][3]=Xl[(m0w+i*16+g+8)*12+t+4];
            }
#pragma unroll
            for (int j = 0; j < 8; j++) {
                int n = n0w + j*8 + g;
                uint32_t bH[2] = {Wh[t*136+n], Wh[(t+4)*136+n]};
                uint32_t bL[2] = {Wl[t*136+n], Wl[(t+4)*136+n]};
#pragma unroll
                for (int i = 0; i < 2; i++) {
                    mma16(acc[i][j], aH[i], bH);
                    mma16(acc[i][j], aH[i], bL);
                    mma16(acc[i][j], aL[i], bH);
                }
            }
        }

#pragma unroll
        for (int i = 0; i < 2; i++) {
#pragma unroll
            for (int j = 0; j < 8; j++) {
                int lc = lcol + n0w + j*8 + 2*t;
                float b0 = bias[lc], b1 = bias[lc+1];
                float c0 = acc[i][j][0] + b0, c1 = acc[i][j][1] + b1;
                float c2 = acc[i][j][2] + b0, c3 = acc[i][j][3] + b1;
                int gr = rowt + m0w + i*16 + g;
                if (sec <= 1) {
                    uint32_t* oph = sec==0 ? g_qph : g_kph;
                    uint32_t* opl = sec==0 ? g_qpl : g_kpl;
                    uint32_t h0,l0,h1,l1,h2,l2,h3,l3;
                    splitb(c0,h0,l0); splitb(c1,h1,l1); splitb(c2,h2,l2); splitb(c3,h3,l3);
                    int pc = lc >> 1;
                    oph[(size_t)gr*512 + pc]     = h0 | (h1<<16);
                    opl[(size_t)gr*512 + pc]     = l0 | (l1<<16);
                    oph[(size_t)(gr+8)*512 + pc] = h2 | (h3<<16);
                    opl[(size_t)(gr+8)*512 + pc] = l2 | (l3<<16);
                } else {
                    c0=fmaxf(c0,0.f); c1=fmaxf(c1,0.f); c2=fmaxf(c2,0.f); c3=fmaxf(c3,0.f);
                    *(float2*)&g_h1[(size_t)gr*H1W + lc]     = make_float2(c0,c1);
                    *(float2*)&g_h1[(size_t)(gr+8)*H1W + lc] = make_float2(c2,c3);
                }
            }
        }
    } else {
        // ---------------- vg path (tf32 single, R12 tiling) ----------------
        uint32_t* Xs = SB;            // [128][20]
        uint32_t* Ws = SB + 2560;     // [16][136]

        const int colt = (blockIdx.y - 18) * 128;
        const float* bias; int lcol, sec;
        if (colt < 1024) { bias=bv; lcol=colt;      sec=2; }
        else             { bias=bg; lcol=colt-1024; sec=3; }

        float acc[2][8][4];
#pragma unroll
        for (int i = 0; i < 2; i++)
#pragma unroll
            for (int j = 0; j < 8; j++)
#pragma unroll
                for (int r = 0; r < 4; r++) acc[i][j][r] = 0.f;

        for (int k0 = 0; k0 < 1024; k0 += 16) {
#pragma unroll
            for (int it = 0; it < 2; it++) {
                int i = tid + it*256;
                int r = i >> 2, kq = (i & 3) << 2;
                *(uint4*)&Xs[r*20 + kq] =
                    *(const uint4*)&g_xtf[(size_t)(rowt + r)*1024 + k0 + kq];
            }
#pragma unroll
            for (int it = 0; it < 2; it++) {
                int i = tid + it*256;
                int kr = i >> 5, c4 = (i & 31) << 2;
                *(uint4*)&Ws[kr*136 + c4] =
                    *(const uint4*)&g_wvg[(size_t)(k0 + kr)*2048 + colt + c4];
            }
            __syncthreads();
#pragma unroll
            for (int ks = 0; ks < 16; ks += 8) {
                uint32_t a[2][4];
#pragma unroll
                for (int i = 0; i < 2; i++) {
                    a[i][0] = Xs[(m0w + i*16 + g    )*20 + ks + t];
                    a[i][1] = Xs[(m0w + i*16 + g + 8)*20 + ks + t];
                    a[i][2] = Xs[(m0w + i*16 + g    )*20 + ks + t + 4];
                    a[i][3] = Xs[(m0w + i*16 + g + 8)*20 + ks + t + 4];
                }
#pragma unroll
                for (int j = 0; j < 8; j++) {
                    uint32_t b[2];
                    b[0] = Ws[(ks + t    )*136 + n0w + j*8 + g];
                    b[1] = Ws[(ks + t + 4)*136 + n0w + j*8 + g];
                    mma8(acc[0][j], a[0], b);
                    mma8(acc[1][j], a[1], b);
                }
            }
            __syncthreads();
        }

#pragma unroll
        for (int i = 0; i < 2; i++) {
#pragma unroll
            for (int j = 0; j < 8; j++) {
                int lc = lcol + n0w + j*8 + 2*t;
                float b0 = bias[lc], b1 = bias[lc + 1];
                float c0 = acc[i][j][0] + b0, c1 = acc[i][j][1] + b1;
                float c2 = acc[i][j][2] + b0, c3 = acc[i][j][3] + b1;
                int gr = rowt + m0w + i*16 + g;
                if (sec == 2) {
                    *(float2*)&g_vh[(size_t)gr*1024 + lc]     = make_float2(tf32f(c0), tf32f(c1));
                    *(float2*)&g_vh[(size_t)(gr+8)*1024 + lc] = make_float2(tf32f(c2), tf32f(c3));
                } else {
                    c0=1.f/(1.f+__expf(-c0)); c1=1.f/(1.f+__expf(-c1));
                    c2=1.f/(1.f+__expf(-c2)); c3=1.f/(1.f+__expf(-c3));
                    *(float2*)&g_gate[(size_t)gr*1024 + lc]     = make_float2(c0,c1);
                    *(float2*)&g_gate[(size_t)(gr+8)*1024 + lc] = make_float2(c2,c3);
                }
            }
        }
    }
}

// ============================================================
// sigma
// ============================================================
__global__ __launch_bounds__(256) void sigma_kernel(
    const float* __restrict__ Wu2, const float* __restrict__ bu2,
    float* __restrict__ out)
{
    const int tid = threadIdx.x, w = tid >> 5, lane = tid & 31;
    const int row = blockIdx.x * 8 + w;
    const float* hr = &g_h1[(size_t)row * H1W];
    float s = 0.f;
#pragma unroll
    for (int j = lane; j < H1W; j += 32) s += hr[j] * Wu2[j];
#pragma unroll
    for (int o = 16; o; o >>= 1) s += __shfl_xor_sync(0xFFFFFFFFu, s, o);
    if (lane == 0) {
        float v = s + bu2[0];
        float sp = (v > 15.f) ? v : log1pf(__expf(v));
        g_sigma[row] = sp + 1e-6f;
        out[SIGMA_OFF + row] = sp + 1e-6f;
    }
}

// ============================================================
// attention: 512 threads, QK^T bf16x3 (Q frags hoisted), PV tf32  [R8/R12]
// ============================================================
#define SM_P    0          // fp32 [32][1028]
#define SM_QH   32896      // u32 [32][36]
#define SM_QL   34048
#define SM_KV   35200      // K: hi[128][36]+lo[128][36] ; V: [128][72]
#define SM_PH   44416      // fp32 [32][132]
#define SM_ISN  48640
#define SM_SCL  49664
#define SM_INVL 49696
#define SM_CS   49728      // fp32 [32][68]
#define SM_TOT  51904
#define ATTN_SMEM_BYTES (SM_TOT*4)

__global__ __launch_bounds__(512) void attn_kernel(float* __restrict__ out)
{
    extern __shared__ float sm[];
    float*    P    = sm + SM_P;
    uint32_t* QH   = (uint32_t*)(sm + SM_QH);
    uint32_t* QL   = (uint32_t*)(sm + SM_QL);
    uint32_t* KH   = (uint32_t*)(sm + SM_KV);
    uint32_t* KL   = KH + 4608;
    uint32_t* VH   = (uint32_t*)(sm + SM_KV);   // union with K
    float*    Ph   = sm + SM_PH;
    float*    isn  = sm + SM_ISN;
    float*    scl  = sm + SM_SCL;
    float*    invl = sm + SM_INVL;
    float*    Cs   = sm + SM_CS;

    const int mt = blockIdx.x, h = blockIdx.y, b = blockIdx.z;
    const int m0 = mt * 32;
    const int tid = threadIdx.x;
    const int w = tid >> 5, lane = tid & 31;
    const int g = lane >> 2, t = lane & 3;

    for (int n = tid; n < 1024; n += 512) isn[n] = 1.f / g_sigma[(b << 10) + n];
    if (tid < 32) scl[tid] = 0.125f / g_sigma[(b << 10) + m0 + tid];

    if (tid < 256) {
        int r = tid >> 3, p4 = (tid & 7) << 2;
        size_t src = ((size_t)(b << 10) + m0 + r)*512 + (h << 5) + p4;
        *(uint4*)&QH[r*36 + p4] = *(const uint4*)&g_qph[src];
        *(uint4*)&QL[r*36 + p4] = *(const uint4*)&g_qpl[src];
    }

    const int kr[2] = { tid >> 3, (tid + 512) >> 3 };
    const int kp4 = (tid & 7) << 2;
    uint4 pkh[2], pkl[2];
#pragma unroll
    for (int it = 0; it < 2; it++) {
        size_t src = ((size_t)(b << 10) + kr[it])*512 + (h << 5) + kp4;
        pkh[it] = *(const uint4*)&g_kph[src];
        pkl[it] = *(const uint4*)&g_kpl[src];
    }

    __syncthreads();

    uint32_t qHf[4][2][4], qLf[4][2][4];
#pragma unroll
    for (int s = 0; s < 4; s++) {
        int ko = s*8;
#pragma unroll
        for (int i = 0; i < 2; i++) {
            qHf[s][i][0]=QH[(i*16+g  )*36+ko+t];   qHf[s][i][1]=QH[(i*16+g+8)*36+ko+t];
            qHf[s][i][2]=QH[(i*16+g  )*36+ko+t+4]; qHf[s][i][3]=QH[(i*16+g+8)*36+ko+t+4];
            qLf[s][i][0]=QL[(i*16+g  )*36+ko+t];   qLf[s][i][1]=QL[(i*16+g+8)*36+ko+t];
            qLf[s][i][2]=QL[(i*16+g  )*36+ko+t+4]; qLf[s][i][3]=QL[(i*16+g+8)*36+ko+t+4];
        }
    }

    for (int c = 0; c < 8; c++) {
        const int n0c = c * 128;
        __syncthreads();
#pragma unroll
        for (int it = 0; it < 2; it++) {
            *(uint4*)&KH[kr[it]*36 + kp4] = pkh[it];
            *(uint4*)&KL[kr[it]*36 + kp4] = pkl[it];
        }
        __syncthreads();
        if (c < 7) {
#pragma unroll
            for (int it = 0; it < 2; it++) {
                size_t src = ((size_t)(b << 10) + (c+1)*128 + kr[it])*512 + (h << 5) + kp4;
                pkh[it] = *(const uint4*)&g_kph[src];
                pkl[it] = *(const uint4*)&g_kpl[src];
            }
        }

        float acc[2][4];
#pragma unroll
        for (int i=0;i<2;i++)
#pragma unroll
            for (int r=0;r<4;r++) acc[i][r] = 0.f;

        const int n = w*8 + g;
#pragma unroll
        for (int s = 0; s < 4; s++) {
            int ko = s*8;
            uint32_t bH[2] = {KH[n*36+ko+t], KH[n*36+ko+t+4]};
            uint32_t bL[2] = {KL[n*36+ko+t], KL[n*36+ko+t+4]};
#pragma unroll
            for (int i = 0; i < 2; i++) {
                mma16(acc[i], qHf[s][i], bH);
                mma16(acc[i], qHf[s][i], bL);
                mma16(acc[i], qLf[s][i], bH);
            }
        }
#pragma unroll
        for (int i = 0; i < 2; i++) {
            int r0 = i*16 + g, r1 = r0 + 8;
            int nl = w*8 + 2*t;
            P[r0*1028 + n0c + nl    ] = __expf(acc[i][0]*scl[r0]*isn[n0c+nl]);
            P[r0*1028 + n0c + nl + 1] = __expf(acc[i][1]*scl[r0]*isn[n0c+nl+1]);
            P[r1*1028 + n0c + nl    ] = __expf(acc[i][2]*scl[r1]*isn[n0c+nl]);
            P[r1*1028 + n0c + nl + 1] = __expf(acc[i][3]*scl[r1]*isn[n0c+nl+1]);
        }
    }

    const int vr[4] = { tid>>4, (tid+512)>>4, (tid+1024)>>4, (tid+1536)>>4 };
    const int vc4 = (tid & 15) << 2;
    uint4 pv[4];
#pragma unroll
    for (int it = 0; it < 4; it++)
        pv[it] = *(const uint4*)&g_vh[((size_t)(b << 10) + vr[it])*1024 + (h << 6) + vc4];

    __syncthreads();
#pragma unroll
    for (int r = w*2; r < w*2 + 2; r++) {
        float s = 0.f;
        for (int n = lane; n < 1024; n += 32) s += P[r*1028 + n];
#pragma unroll
        for (int o = 16; o; o >>= 1) s += __shfl_xor_sync(0xFFFFFFFFu, s, o);
        if (lane == 0) invl[r] = 1.f / s;
    }
    __syncthreads();

    {
        const size_t base = ATTN_OFF + (((size_t)(b*16 + h))*1024 + m0)*1024;
        for (int e = tid; e < 32*256; e += 512) {
            int i = e >> 8, n4 = (e & 255) << 2;
            float4 p = *(float4*)&P[i*1028 + n4];
            float iv = invl[i];
            p.x*=iv; p.y*=iv; p.z*=iv; p.w*=iv;
            *(float4*)&out[base + (size_t)i*1024 + n4] = p;
        }
    }

    float cacc[4] = {0.f, 0.f, 0.f, 0.f};
    const int ihalf = w >> 3, d0 = (w & 7) * 8;
    const int pr = tid >> 4, pjb = (tid & 15) << 3;

    for (int c = 0; c < 8; c++) {
        const int n0c = c * 128;
        __syncthreads();
#pragma unroll
        for (int it = 0; it < 4; it++)
            *(uint4*)&VH[vr[it]*72 + vc4] = pv[it];
#pragma unroll
        for (int jj = 0; jj < 8; jj++)
            Ph[pr*132 + pjb + jj] = tf32f(P[pr*1028 + n0c + pjb + jj]);
        __syncthreads();
        if (c < 7) {
#pragma unroll
            for (int it = 0; it < 4; it++)
                pv[it] = *(const uint4*)&g_vh[((size_t)(b << 10) + (c+1)*128 + vr[it])*1024 + (h << 6) + vc4];
        }
#pragma unroll
        for (int ks = 0; ks < 128; ks += 8) {
            uint32_t aH[4];
            aH[0]=__float_as_uint(Ph[(ihalf*16+g  )*132+ks+t]);
            aH[1]=__float_as_uint(Ph[(ihalf*16+g+8)*132+ks+t]);
            aH[2]=__float_as_uint(Ph[(ihalf*16+g  )*132+ks+t+4]);
            aH[3]=__float_as_uint(Ph[(ihalf*16+g+8)*132+ks+t+4]);
            uint32_t bb[2] = {VH[(ks+t)*72 + d0 + g], VH[(ks+t+4)*72 + d0 + g]};
            mma8(cacc, aH, bb);
        }
    }
    __syncthreads();

    {
        int r0 = ihalf*16 + g, r1 = r0 + 8;
        int d = d0 + 2*t;
        float g0 = g_gate[((size_t)(b<<10) + m0 + r0)*1024 + (h<<6) + d];
        float g1 = g_gate[((size_t)(b<<10) + m0 + r0)*1024 + (h<<6) + d + 1];
        float g2 = g_gate[((size_t)(b<<10) + m0 + r1)*1024 + (h<<6) + d];
        float g3 = g_gate[((size_t)(b<<10) + m0 + r1)*1024 + (h<<6) + d + 1];
        Cs[r0*68 + d    ] = cacc[0] * invl[r0] * g0;
        Cs[r0*68 + d + 1] = cacc[1] * invl[r0] * g1;
        Cs[r1*68 + d    ] = cacc[2] * invl[r1] * g2;
        Cs[r1*68 + d + 1] = cacc[3] * invl[r1] * g3;
    }
    __syncthreads();
    if (tid < 64) {
        float s = 0.f;
#pragma unroll
        for (int i = 0; i < 32; i++) s += Cs[i*68 + tid];
        g_part[(((b << 4) + h)*32 + mt)*64 + tid] = s * (1.f/1024.f);
    }
}

// ============================================================
// z = colmean @ Wo + bo
// ============================================================
__global__ __launch_bounds__(256) void z_kernel(
    const float* __restrict__ Wo, const float* __restrict__ bo,
    float* __restrict__ out)
{
    __shared__ float cm[1024];
    __shared__ float red[4][64];
    const int b = blockIdx.x, oc = blockIdx.y;

    for (int c = threadIdx.x; c < 1024; c += 256) {
        int hh = c >> 6, d = c & 63;
        const float* pp = &g_part[(size_t)(((b << 4) + hh)*32)*64 + d];
        float s = 0.f;
#pragma unroll
        for (int tt = 0; tt < 32; tt++) s += pp[tt*64];
        cm[c] = s;
    }
    __syncthreads();

    const int oi = threadIdx.x & 63, ks = threadIdx.x >> 6;
    const int o = oc*64 + oi;
    float s = 0.f;
#pragma unroll 4
    for (int k = ks*256; k < ks*256 + 256; k++) s += cm[k] * Wo[(size_t)k*1024 + o];
    red[ks][oi] = s;
    __syncthreads();
    if (threadIdx.x < 64) {
        float r = red[0][threadIdx.x] + red[1][threadIdx.x]
                + red[2][threadIdx.x] + red[3][threadIdx.x] + bo[oc*64 + threadIdx.x];
        out[Z_OFF + (size_t)b*1024 + oc*64 + threadIdx.x] = r;
    }
}

// ============================================================
extern "C" void kernel_launch(void* const* d_in, const int* in_sizes, int n_in,
                              void* d_out, int out_size)
{
    const float* x   = (const float*)d_in[0];
    const float* Wq  = (const float*)d_in[1];
    const float* bq  = (const float*)d_in[2];
    const float* Wk  = (const float*)d_in[3];
    const float* bk  = (const float*)d_in[4];
    const float* Wv  = (const float*)d_in[5];
    const float* bv  = (const float*)d_in[6];
    const float* Wg  = (const float*)d_in[7];
    const float* bg  = (const float*)d_in[8];
    const float* Wo  = (const float*)d_in[9];
    const float* bo  = (const float*)d_in[10];
    const float* Wu1 = (const float*)d_in[11];
    const float* bu1 = (const float*)d_in[12];
    const float* Wu2 = (const float*)d_in[13];
    const float* bu2 = (const float*)d_in[14];
    float* out = (float*)d_out;

    conv_x_kernel<<<8192, 256>>>(x);
    conv_w_kernel<<<1152, 256>>>(Wq, Wk, Wu1);
    conv_wvg_kernel<<<2048, 256>>>(Wv, Wg);
    proj_kernel<<<dim3(64, 34), 256>>>(bq, bk, bu1, bv, bg);
    sigma_kernel<<<1024, 256>>>(Wu2, bu2, out);
    cudaFuncSetAttribute(attn_kernel, cudaFuncAttributeMaxDynamicSharedMemorySize,
                         ATTN_SMEM_BYTES);
    attn_kernel<<<dim3(32, 16, 8), 512, ATTN_SMEM_BYTES>>>(out);
    z_kernel<<<dim3(8, 16), 256>>>(Wo, bo, out);
}